// round 14
// baseline (speedup 1.0000x reference)
#include <cuda_runtime.h>
#include <math.h>
#include <stdint.h>

#define NB 2
#define SQ 2048
#define NTOK 4096
#define DM 512
#define NH 8
#define DK 64
#define NL 6
#define DFF 2048
#define NV 1024
#define QKVW 1536

// ---------------- scratch ----------------
__device__ float g_x   [NTOK * DM];
__device__ float g_h   [NTOK * DM];
__device__ float g_qkv [NTOK * QKVW];
__device__ float g_ff  [NTOK * DFF];
__device__ float g_vt  [16 * 64 * SQ];
__device__ float g_wqkvT[NL * QKVW * DM];
__device__ float g_woT  [NL * DM * DM];
__device__ float g_w1T  [NL * DFF * DM];
__device__ float g_w2T  [NL * DM * DFF];
__device__ float g_outwT[NV * DM];
__device__ float g_bqkv [NL * QKVW];

// ---------------- helpers ----------------
__device__ __forceinline__ uint32_t f2tf(float f) {
    uint32_t r;
    asm("cvt.rna.tf32.f32 %0, %1;" : "=r"(r) : "f"(f));
    return r;
}
__device__ __forceinline__ float tfround(float f) { return __uint_as_float(f2tf(f)); }
__device__ __forceinline__ void mma8(float* c, const uint32_t* a, const uint32_t* b) {
    asm volatile(
        "mma.sync.aligned.m16n8k8.row.col.f32.tf32.tf32.f32 "
        "{%0,%1,%2,%3}, {%4,%5,%6,%7}, {%8,%9}, {%0,%1,%2,%3};\n"
        : "+f"(c[0]), "+f"(c[1]), "+f"(c[2]), "+f"(c[3])
        : "r"(a[0]), "r"(a[1]), "r"(a[2]), "r"(a[3]), "r"(b[0]), "r"(b[1]));
}
__device__ __forceinline__ void cpa16(uint32_t dst, const void* src) {
    asm volatile("cp.async.cg.shared.global [%0], [%1], 16;" :: "r"(dst), "l"(src));
}
#define CP_COMMIT() asm volatile("cp.async.commit_group;" ::: "memory")
#define CP_WAIT(n)  asm volatile("cp.async.wait_group %0;" :: "n"(n) : "memory")
__device__ __forceinline__ uint32_t smem_u32(const void* p) {
    uint32_t a;
    asm("{ .reg .u64 t; cvta.to.shared.u64 t, %1; cvt.u32.u64 %0, t; }" : "=r"(a) : "l"(p));
    return a;
}

#define GP 36

// ======== GEMM epilogue ========
// mode: 0 plain, 1 relu+tf32round, 2 tf32round (after residual if any)
__device__ __forceinline__ void gemm_epilogue(float acc[4][4][4],
                                              const float* bias, const float* R,
                                              float* C, float* VT,
                                              int row0, int col0, int M, int mode,
                                              int wm, int wn, int gr, int lc) {
    bool vcols = (VT != nullptr) && (col0 >= 1024);
    #pragma unroll
    for (int mt = 0; mt < 4; mt++) {
        int r = row0 + wm * 64 + mt * 16 + gr;
        #pragma unroll
        for (int nt = 0; nt < 4; nt++) {
            int c = col0 + wn * 32 + nt * 8 + lc * 2;
            float b0 = bias[c], b1 = bias[c + 1];
            #pragma unroll
            for (int h2 = 0; h2 < 2; h2++) {
                int rr = r + h2 * 8;
                size_t off = (size_t)rr * M + c;
                float v0 = acc[mt][nt][h2 * 2 + 0] + b0;
                float v1 = acc[mt][nt][h2 * 2 + 1] + b1;
                if (R) { float2 rv = *(const float2*)(R + off); v0 += rv.x; v1 += rv.y; }
                if (mode == 1) {
                    v0 = tfround(fmaxf(v0, 0.f)); v1 = tfround(fmaxf(v1, 0.f));
                } else if (mode == 2) {
                    v0 = tfround(v0); v1 = tfround(v1);
                }
                if (!vcols) {
                    *(float2*)(C + off) = make_float2(v0, v1);
                } else {
                    int bbq = rr >> 11, s = rr & (SQ - 1);
                    int dc = c - 1024;
                    int hv = dc >> 6, d = dc & 63;
                    float* vp = VT + ((size_t)((bbq << 3) + hv) * 64 + d) * SQ + s;
                    vp[0]  = v0;
                    vp[SQ] = v1;
                }
            }
        }
    }
}

// ======== cp.async GEMM: A/Wt pre-rounded to tf32 ========
#define CPSTAGE 9216
#define GEMM_CP_SMEM (3 * CPSTAGE * 4)

__global__ __launch_bounds__(256) void gemm_cp(const float* __restrict__ A,
                                               const float* __restrict__ Wt,
                                               const float* __restrict__ bias,
                                               const float* __restrict__ R,
                                               float* __restrict__ C,
                                               float* __restrict__ VT,
                                               int K, int M, int mode) {
    extern __shared__ uint32_t sm[];
    uint32_t sb = smem_u32(sm);
    int t = threadIdx.x, lane = t & 31, wid = t >> 5;
    int wm = wid & 1, wn = wid >> 1;
    int gr = lane >> 2, lc = lane & 3;
    int row0 = blockIdx.y * 128, col0 = blockIdx.x * 128;
    const int NC = K >> 5;

    int half = t >> 7, li = t & 127;
    const float* src = half ? (Wt + (size_t)col0 * K) : (A + (size_t)row0 * K);

    float acc[4][4][4];
    #pragma unroll
    for (int i = 0; i < 4; i++)
        #pragma unroll
        for (int j = 0; j < 4; j++)
            #pragma unroll
            for (int k = 0; k < 4; k++) acc[i][j][k] = 0.f;

    auto issue = [&](int c, int st) {
        uint32_t dbase = sb + (st * CPSTAGE + half * 4608) * 4;
        const float* s0 = src + c * 32;
        #pragma unroll
        for (int j = 0; j < 8; j++) {
            int seg = j * 128 + li, r = seg >> 3, p = seg & 7;
            cpa16(dbase + (r * GP + p * 4) * 4, s0 + (size_t)r * K + p * 4);
        }
    };

    issue(0, 0); CP_COMMIT();
    if (NC > 1) { issue(1, 1); CP_COMMIT(); }

    for (int c = 0; c < NC; c++) {
        if (c + 1 < NC) { CP_WAIT(1); } else { CP_WAIT(0); }
        __syncthreads();
        if (c + 2 < NC) { issue(c + 2, (c + 2) % 3); CP_COMMIT(); }

        const uint32_t* S = sm + (c % 3) * CPSTAGE;
        const uint32_t* Abase = S + (wm * 64 + gr) * GP + lc;
        const uint32_t* Bbase = S + 4608 + (wn * 32 + gr) * GP + lc;
        #pragma unroll
        for (int ks = 0; ks < 4; ks++) {
            uint32_t a[4][4], b[4][2];
            #pragma unroll
            for (int mt = 0; mt < 4; mt++) {
                const uint32_t* p = Abase + mt * 16 * GP + ks * 8;
                a[mt][0] = p[0]; a[mt][1] = p[8 * GP]; a[mt][2] = p[4]; a[mt][3] = p[8 * GP + 4];
            }
            #pragma unroll
            for (int nt = 0; nt < 4; nt++) {
                const uint32_t* p = Bbase + nt * 8 * GP + ks * 8;
                b[nt][0] = p[0]; b[nt][1] = p[4];
            }
            #pragma unroll
            for (int mt = 0; mt < 4; mt++)
                #pragma unroll
                for (int nt = 0; nt < 4; nt++)
                    mma8(acc[mt][nt], a[mt], b[nt]);
        }
    }

    gemm_epilogue(acc, bias, R, C, VT, row0, col0, M, mode, wm, wn, gr, lc);
}

// ---------------- flash attention v3 (R9-proven; R13 epilogue rounding) ----------------
#define AP 68
#define OQ 0
#define OKB 4352
#define OPS 13056
#define OST 17408
#define ATTN_SMEM ((OST + 192) * 4)

__global__ __launch_bounds__(128) void attn_mma(const float* __restrict__ qkv,
                                                const float* __restrict__ vt,
                                                float* __restrict__ out) {
    extern __shared__ uint32_t smu[];
    uint32_t sb = smem_u32(smu);
    int qt = gridDim.x - 1 - blockIdx.x;
    int bh = blockIdx.y, bb = bh >> 3, hh = bh & 7;
    int t = threadIdx.x, lane = t & 31, wid = t >> 5;
    int gr = lane >> 2, lc = lane & 3;
    int mrow = wid * 16 + gr;
    const size_t base = (size_t)bb * SQ * QKVW + hh * DK;
    const float* qb = qkv + base + (size_t)qt * 64 * QKVW;
    const float* vbase = vt + (size_t)bh * 64 * SQ;

    float* sm_m  = (float*)(smu + OST);
    float* sm_l  = sm_m + 64;
    float* sm_rs = sm_m + 128;
    uint32_t* Qs = smu + OQ;
    float*    Ps = (float*)(smu + OPS);

    #pragma unroll
    for (int i = 0; i < 8; i++) {
        int f = i * 128 + t, r = f >> 4, d4 = (f & 15) << 2;
        cpa16(sb + (OQ + r * AP + d4) * 4, qb + (size_t)r * QKVW + d4);
    }
    {
        const float* kb = qkv + base + 512;
        #pragma unroll
        for (int i = 0; i < 8; i++) {
            int f = i * 128 + t, r = f >> 4, d4 = (f & 15) << 2;
            cpa16(sb + (OKB + r * AP + d4) * 4, kb + (size_t)r * QKVW + d4);
        }
    }
    CP_COMMIT();

    if (lane < 16) { sm_m[wid * 16 + lane] = -1e30f; sm_l[wid * 16 + lane] = 0.f; }

    float co[8][4];
    #pragma unroll
    for (int i = 0; i < 8; i++)
        #pragma unroll
        for (int j = 0; j < 4; j++) co[i][j] = 0.f;

    for (int kt = 0; kt <= qt; kt++) {
        int cur = kt & 1;
        if (kt == 0) { CP_WAIT(0); __syncthreads(); }
        const uint32_t* Kb = smu + OKB + cur * 4352;

        float cs[8][4];
        #pragma unroll
        for (int i = 0; i < 8; i++)
            #pragma unroll
            for (int j = 0; j < 4; j++) cs[i][j] = 0.f;
        {
            const uint32_t* Abase = Qs + mrow * AP + lc;
            const uint32_t* Bbase = Kb + gr * AP + lc;
            #pragma unroll
            for (int ks = 0; ks < 8; ks++) {
                uint32_t a[4];
                const uint32_t* p = Abase + ks * 8;
                a[0] = p[0]; a[1] = p[8 * AP]; a[2] = p[4]; a[3] = p[8 * AP + 4];
                #pragma unroll
                for (int nt = 0; nt < 8; nt++) {
                    const uint32_t* q2 = Bbase + nt * 8 * AP + ks * 8;
                    uint32_t b[2] = {q2[0], q2[4]};
                    mma8(cs[nt], a, b);
                }
            }
        }
        #pragma unroll
        for (int nt = 0; nt < 8; nt++) {
            int c = nt * 8 + lc * 2;
            *(float2*)(Ps + mrow * AP + c)       = make_float2(cs[nt][0], cs[nt][1]);
            *(float2*)(Ps + (mrow + 8) * AP + c) = make_float2(cs[nt][2], cs[nt][3]);
        }
        __syncthreads();

        #pragma unroll
        for (int i = 0; i < 8; i++) {
            int f = i * 128 + t, d = f >> 4, k4 = (f & 15) << 2;
            cpa16(sb + (OKB + cur * 4352 + d * AP + k4) * 4,
                  vbase + (size_t)d * SQ + kt * 64 + k4);
        }
        CP_COMMIT();
        if (kt < qt) {
            const float* kb = qkv + base + 512 + (size_t)(kt + 1) * 64 * QKVW;
            #pragma unroll
            for (int i = 0; i < 8; i++) {
                int f = i * 128 + t, r = f >> 4, d4 = (f & 15) << 2;
                cpa16(sb + (OKB + (cur ^ 1) * 4352 + r * AP + d4) * 4,
                      kb + (size_t)r * QKVW + d4);
            }
            CP_COMMIT();
        }

        {
            int r = t >> 1, half = t & 1;
            int qrow = qt * 64 + r;
            int kbase0 = kt * 64 + half * 32;
            float* rowp = Ps + r * AP + half * 32;
            float vals[32];
            float mx = -1e30f;
            bool edge = (kt == qt);
            #pragma unroll
            for (int j = 0; j < 32; j += 4) {
                float4 v4 = *(const float4*)(rowp + j);
                float w0 = v4.x * 0.125f, w1 = v4.y * 0.125f;
                float w2 = v4.z * 0.125f, w3 = v4.w * 0.125f;
                if (edge) {
                    if (kbase0 + j + 0 > qrow) w0 = -1e30f;
                    if (kbase0 + j + 1 > qrow) w1 = -1e30f;
                    if (kbase0 + j + 2 > qrow) w2 = -1e30f;
                    if (kbase0 + j + 3 > qrow) w3 = -1e30f;
                }
                vals[j] = w0; vals[j+1] = w1; vals[j+2] = w2; vals[j+3] = w3;
                mx = fmaxf(mx, fmaxf(fmaxf(w0, w1), fmaxf(w2, w3)));
            }
            mx = fmaxf(mx, __shfl_xor_sync(0xffffffffu, mx, 1));
            float mo = sm_m[r];
            float mn = fmaxf(mo, mx);
            float rs = __expf(mo - mn);
            float ssum = 0.f;
            #pragma unroll
            for (int j = 0; j < 32; j += 4) {
                float p0 = __expf(vals[j]   - mn), p1 = __expf(vals[j+1] - mn);
                float p2 = __expf(vals[j+2] - mn), p3 = __expf(vals[j+3] - mn);
                ssum += (p0 + p1) + (p2 + p3);
                *(uint4*)(rowp + j) = make_uint4(f2tf(p0), f2tf(p1), f2tf(p2), f2tf(p3));
            }
            ssum += __shfl_xor_sync(0xffffffffu, ssum, 1);
            if (!half) { sm_l[r] = sm_l[r] * rs + ssum; sm_m[r] = mn; sm_rs[r] = rs; }
        }

        CP_WAIT(0);
        __syncthreads();

        {
            float rs0 = sm_rs[mrow], rs1 = sm_rs[mrow + 8];
            #pragma unroll
            for (int nt = 0; nt < 8; nt++) {
                co[nt][0] *= rs0; co[nt][1] *= rs0;
                co[nt][2] *= rs1; co[nt][3] *= rs1;
            }
            const uint32_t* Pb = (const uint32_t*)Ps + mrow * AP + lc;
            const uint32_t* Bbase = Kb + gr * AP + lc;
            #pragma unroll
            for (int ks = 0; ks < 8; ks++) {
                uint32_t a[4];
                const uint32_t* p = Pb + ks * 8;
                a[0] = p[0]; a[1] = p[8 * AP]; a[2] = p[4]; a[3] = p[8 * AP + 4];
                #pragma unroll
                for (int nt = 0; nt < 8; nt++) {
                    const uint32_t* q2 = Bbase + nt * 8 * AP + ks * 8;
                    uint32_t b[2] = {q2[0], q2[4]};
                    mma8(co[nt], a, b);
                }
            }
        }
    }

    float inv0 = 1.f / sm_l[mrow], inv1 = 1.f / sm_l[mrow + 8];
    float* ob = out + ((size_t)bb * SQ + (size_t)qt * 64) * DM + hh * DK;
    #pragma unroll
    for (int nt = 0; nt < 8; nt++) {
        int c = nt * 8 + lc * 2;
        *(float2*)(ob + (size_t)mrow * DM + c) =
            make_float2(tfround(co[nt][0] * inv0), tfround(co[nt][1] * inv0));
        *(float2*)(ob + (size_t)(mrow + 8) * DM + c) =
            make_float2(tfround(co[nt][2] * inv1), tfround(co[nt][3] * inv1));
    }
}

// ---------------- weight transposes (write tf32-rounded) ----------------
__global__ __launch_bounds__(256) void transpose_k(const float* __restrict__ in,
                                                   float* __restrict__ out,
                                                   int R, int C,
                                                   size_t in_z, size_t out_z) {
    __shared__ float tbuf[32][33];
    in  += blockIdx.z * in_z;
    out += blockIdx.z * out_z;
    int c0 = blockIdx.x * 32, r0 = blockIdx.y * 32;
    #pragma unroll
    for (int i = 0; i < 32; i += 8)
        tbuf[threadIdx.y + i][threadIdx.x] = in[(size_t)(r0 + threadIdx.y + i) * C + c0 + threadIdx.x];
    __syncthreads();
    #pragma unroll
    for (int i = 0; i < 32; i += 8)
        out[(size_t)(c0 + threadIdx.y + i) * R + r0 + threadIdx.x] =
            tfround(tbuf[threadIdx.x][threadIdx.y + i]);
}

__global__ __launch_bounds__(256) void transpose_qkv(const float* __restrict__ wq,
                                                     const float* __restrict__ wk,
                                                     const float* __restrict__ wv,
                                                     float* __restrict__ outT) {
    __shared__ float tbuf[32][33];
    int z = blockIdx.z, l = z / 3, w = z % 3;
    const float* in = (w == 0 ? wq : w == 1 ? wk : wv) + (size_t)l * DM * DM;
    float* out = outT + (size_t)l * QKVW * DM + (size_t)w * DM * DM;
    int c0 = blockIdx.x * 32, r0 = blockIdx.y * 32;
    #pragma unroll
    for (int i = 0; i < 32; i += 8)
        tbuf[threadIdx.y + i][threadIdx.x] = in[(size_t)(r0 + threadIdx.y + i) * DM + c0 + threadIdx.x];
    __syncthreads();
    #pragma unroll
    for (int i = 0; i < 32; i += 8)
        out[(size_t)(c0 + threadIdx.y + i) * DM + r0 + threadIdx.x] =
            tfround(tbuf[threadIdx.x][threadIdx.y + i]);
}

__global__ __launch_bounds__(256) void biaspack_kernel(const float* __restrict__ bq,
                                                       const float* __restrict__ bk,
                                                       const float* __restrict__ bv,
                                                       float* __restrict__ dst) {
    int idx = blockIdx.x * 256 + threadIdx.x;
    if (idx >= NL * QKVW) return;
    int l = idx / QKVW, j = idx % QKVW;
    float v;
    if (j < 512)       v = bq[l * 512 + j];
    else if (j < 1024) v = bk[l * 512 + j - 512];
    else               v = bv[l * 512 + j - 1024];
    dst[idx] = v;
}

// ---------------- fused embed + layer-0 ln1 (identical arithmetic) ----------------
__global__ __launch_bounds__(256) void embed_ln(const int* __restrict__ ids,
                                                const float* __restrict__ emb,
                                                const float* __restrict__ w,
                                                const float* __restrict__ bias,
                                                float* __restrict__ x,
                                                float* __restrict__ y) {
    __shared__ float sred[16];
    int row = blockIdx.x, t = threadIdx.x;
    int s = row & (SQ - 1);
    int tok = ids[row];
    // embed values, exact formula of embed_kernel
    float v0, v1;
    {
        int d = t, i2 = d & ~1;
        float div = expf(-(float)i2 * (9.210340371976184f / 512.0f));
        float ang = (float)s * div;
        float pe = (d & 1) ? cosf(ang) : sinf(ang);
        v0 = emb[(size_t)tok * DM + d] + pe;
    }
    {
        int d = t + 256, i2 = d & ~1;
        float div = expf(-(float)i2 * (9.210340371976184f / 512.0f));
        float ang = (float)s * div;
        float pe = (d & 1) ? cosf(ang) : sinf(ang);
        v1 = emb[(size_t)tok * DM + d] + pe;
    }
    float* xr = x + (size_t)row * DM;
    xr[t] = v0;
    xr[t + 256] = v1;
    // LN — body identical to ln_kernel
    float ssum = v0 + v1;
    #pragma unroll
    for (int off = 16; off; off >>= 1) ssum += __shfl_xor_sync(0xffffffffu, ssum, off);
    if ((t & 31) == 0) sred[t >> 5] = ssum;
    __syncthreads();
    float tot = 0.f;
    #pragma unroll
    for (int i = 0; i < 8; i++) tot += sred[i];
    float mu = tot * (1.0f / DM);
    float d0 = v0 - mu, d1 = v1 - mu;
    float s2 = d0 * d0 + d1 * d1;
    #pragma unroll
    for (int off = 16; off; off >>= 1) s2 += __shfl_xor_sync(0xffffffffu, s2, off);
    if ((t & 31) == 0) sred[8 + (t >> 5)] = s2;
    __syncthreads();
    float tot2 = 0.f;
    #pragma unroll
    for (int i = 0; i < 8; i++) tot2 += sred[8 + i];
    float rstd = rsqrtf(tot2 * (1.0f / DM) + 1e-5f);
    float* yr = y + (size_t)row * DM;
    yr[t]       = tfround(d0 * rstd * w[t]       + bias[t]);
    yr[t + 256] = tfround(d1 * rstd * w[t + 256] + bias[t + 256]);
}

// ---------------- layernorm: 2 rows per 512-thread block (per-row math identical) ----------------
__global__ __launch_bounds__(512) void ln_kernel(const float* __restrict__ x,
                                                 const float* __restrict__ w,
                                                 const float* __restrict__ bias,
                                                 float* __restrict__ y) {
    __shared__ float sred[32];        // 16 per half
    int half = threadIdx.x >> 8;
    int t = threadIdx.x & 255;
    int row = blockIdx.x * 2 + half;
    float* sr = sred + half * 16;
    const float* xr = x + (size_t)row * DM;
    float v0 = xr[t];
    float v1 = xr[t + 256];
    float s = v0 + v1;
    #pragma unroll
    for (int off = 16; off; off >>= 1) s += __shfl_xor_sync(0xffffffffu, s, off);
    if ((t & 31) == 0) sr[t >> 5] = s;
    __syncthreads();
    float tot = 0.f;
    #pragma unroll
    for (int i = 0; i < 8; i++) tot += sr[i];
    float mu = tot * (1.0f / DM);
    float d0 = v0 - mu, d1 = v1 - mu;
    float s2 = d0 * d0 + d1 * d1;
    #pragma unroll
    for (int off = 16; off; off >>= 1) s2 += __shfl_xor_sync(0xffffffffu, s2, off);
    if ((t & 31) == 0) sr[8 + (t >> 5)] = s2;
    __syncthreads();
    float tot2 = 0.f;
    #pragma unroll
    for (int i = 0; i < 8; i++) tot2 += sr[8 + i];
    float rstd = rsqrtf(tot2 * (1.0f / DM) + 1e-5f);
    float* yr = y + (size_t)row * DM;
    yr[t]       = tfround(d0 * rstd * w[t]       + bias[t]);
    yr[t + 256] = tfround(d1 * rstd * w[t + 256] + bias[t + 256]);
}

// ---------------- host ----------------
static void run_gemm_cp(const float* A, const float* Wt, const float* bias, const float* R,
                        float* C, float* VT, int K, int M, int mode) {
    gemm_cp<<<dim3(M / 128, NTOK / 128), 256, GEMM_CP_SMEM>>>(A, Wt, bias, R, C, VT, K, M, mode);
}

extern "C" void kernel_launch(void* const* d_in, const int* in_sizes, int n_in,
                              void* d_out, int out_size) {
    (void)in_sizes; (void)n_in; (void)out_size;
    const int*   ids  = (const int*)  d_in[0];
    const float* emb  = (const float*)d_in[1];
    const float* wq   = (const float*)d_in[2];
    const float* bq   = (const float*)d_in[3];
    const float* wk   = (const float*)d_in[4];
    const float* bk   = (const float*)d_in[5];
    const float* wv   = (const float*)d_in[6];
    const float* bv   = (const float*)d_in[7];
    const float* wo   = (const float*)d_in[8];
    const float* bo   = (const float*)d_in[9];
    const float* ln1w = (const float*)d_in[10];
    const float* ln1b = (const float*)d_in[11];
    const float* ln2w = (const float*)d_in[12];
    const float* ln2b = (const float*)d_in[13];
    const float* w1   = (const float*)d_in[14];
    const float* b1   = (const float*)d_in[15];
    const float* w2   = (const float*)d_in[16];
    const float* b2   = (const float*)d_in[17];
    const float* outw = (const float*)d_in[18];
    const float* outb = (const float*)d_in[19];

    float *x, *h, *qkv, *ff, *vt, *wqkvT, *woT, *w1T, *w2T, *outwT, *bqkv;
    cudaGetSymbolAddress((void**)&x,     g_x);
    cudaGetSymbolAddress((void**)&h,     g_h);
    cudaGetSymbolAddress((void**)&qkv,   g_qkv);
    cudaGetSymbolAddress((void**)&ff,    g_ff);
    cudaGetSymbolAddress((void**)&vt,    g_vt);
    cudaGetSymbolAddress((void**)&wqkvT, g_wqkvT);
    cudaGetSymbolAddress((void**)&woT,   g_woT);
    cudaGetSymbolAddress((void**)&w1T,   g_w1T);
    cudaGetSymbolAddress((void**)&w2T,   g_w2T);
    cudaGetSymbolAddress((void**)&outwT, g_outwT);
    cudaGetSymbolAddress((void**)&bqkv,  g_bqkv);

    cudaFuncSetAttribute(gemm_cp,  cudaFuncAttributeMaxDynamicSharedMemorySize, GEMM_CP_SMEM);
    cudaFuncSetAttribute(attn_mma, cudaFuncAttributeMaxDynamicSharedMemorySize, ATTN_SMEM);

    dim3 tb(32, 8);

    // Ordered so the layer-0 QKV gemm_cp is our 4th launch (ncu capture slot).
    embed_ln<<<NTOK, 256>>>(ids, emb, ln1w, ln1b, x, h);                       // 1
    transpose_qkv<<<dim3(16, 16, 3 * NL), tb>>>(wq, wk, wv, wqkvT);            // 2
    biaspack_kernel<<<(NL * QKVW + 255) / 256, 256>>>(bq, bk, bv, bqkv);       // 3
    run_gemm_cp(h, wqkvT, bqkv, nullptr, qkv, vt, DM, QKVW, 2);                // 4 <- ncu
    transpose_k<<<dim3(16, 16, NL), tb>>>(wo, woT, DM, DM, (size_t)DM*DM, (size_t)DM*DM);
    transpose_k<<<dim3(DFF/32, 16, NL), tb>>>(w1, w1T, DM, DFF, (size_t)DM*DFF, (size_t)DM*DFF);
    transpose_k<<<dim3(16, DFF/32, NL), tb>>>(w2, w2T, DFF, DM, (size_t)DM*DFF, (size_t)DM*DFF);
    transpose_k<<<dim3(NV/32, 16, 1),   tb>>>(outw, outwT, DM, NV, 0, 0);

    for (int l = 0; l < NL; l++) {
        size_t offD = (size_t)l * DM;
        size_t offF = (size_t)l * DFF;

        if (l > 0) {
            ln_kernel<<<NTOK / 2, 512>>>(x, ln1w + offD, ln1b + offD, h);
            run_gemm_cp(h, wqkvT + (size_t)l * QKVW * DM, bqkv + (size_t)l * QKVW, nullptr,
                        qkv, vt, DM, QKVW, 2);
        }
        attn_mma<<<dim3(SQ / 64, NB * NH), 128, ATTN_SMEM>>>(qkv, vt, h);
        run_gemm_cp(h, woT + (size_t)l * DM * DM, bo + offD, nullptr, x, nullptr, DM, DM, 0);
        ln_kernel<<<NTOK / 2, 512>>>(x, ln2w + offD, ln2b + offD, h);
        run_gemm_cp(h, w1T + (size_t)l * DM * DFF, b1 + offF, nullptr, ff, nullptr, DM, DFF, 1);
        // final layer: round x (it only feeds the logits GEMM; staging would round anyway)
        run_gemm_cp(ff, w2T + (size_t)l * DM * DFF, b2 + offD, x /*residual*/, x, nullptr,
                    DFF, DM, (l == NL - 1) ? 2 : 0);
    }

    // x pre-rounded by layer-5 w2 epilogue -> raw cp.async staging is bit-identical
    run_gemm_cp(x, outwT, outb, nullptr, (float*)d_out, nullptr, DM, NV, 0);
}

// round 15
// speedup vs baseline: 1.0777x; 1.0777x over previous
#include <cuda_runtime.h>
#include <math.h>
#include <stdint.h>

#define NB 2
#define SQ 2048
#define NTOK 4096
#define DM 512
#define NH 8
#define DK 64
#define NL 6
#define DFF 2048
#define NV 1024
#define QKVW 1536

// ---------------- scratch ----------------
__device__ float g_x   [NTOK * DM];
__device__ float g_h   [NTOK * DM];
__device__ float g_qkv [NTOK * QKVW];
__device__ float g_ff  [NTOK * DFF];
__device__ float g_vt  [16 * 64 * SQ];
__device__ float g_wqkvT[NL * QKVW * DM];
__device__ float g_woT  [NL * DM * DM];
__device__ float g_w1T  [NL * DFF * DM];
__device__ float g_w2T  [NL * DM * DFF];
__device__ float g_outwT[NV * DM];
__device__ float g_bqkv [NL * QKVW];

// ---------------- helpers ----------------
__device__ __forceinline__ uint32_t f2tf(float f) {
    uint32_t r;
    asm("cvt.rna.tf32.f32 %0, %1;" : "=r"(r) : "f"(f));
    return r;
}
__device__ __forceinline__ float tfround(float f) { return __uint_as_float(f2tf(f)); }
__device__ __forceinline__ void mma8(float* c, const uint32_t* a, const uint32_t* b) {
    asm volatile(
        "mma.sync.aligned.m16n8k8.row.col.f32.tf32.tf32.f32 "
        "{%0,%1,%2,%3}, {%4,%5,%6,%7}, {%8,%9}, {%0,%1,%2,%3};\n"
        : "+f"(c[0]), "+f"(c[1]), "+f"(c[2]), "+f"(c[3])
        : "r"(a[0]), "r"(a[1]), "r"(a[2]), "r"(a[3]), "r"(b[0]), "r"(b[1]));
}
__device__ __forceinline__ void cpa16(uint32_t dst, const void* src) {
    asm volatile("cp.async.cg.shared.global [%0], [%1], 16;" :: "r"(dst), "l"(src));
}
#define CP_COMMIT() asm volatile("cp.async.commit_group;" ::: "memory")
#define CP_WAIT(n)  asm volatile("cp.async.wait_group %0;" :: "n"(n) : "memory")
__device__ __forceinline__ uint32_t smem_u32(const void* p) {
    uint32_t a;
    asm("{ .reg .u64 t; cvta.to.shared.u64 t, %1; cvt.u32.u64 %0, t; }" : "=r"(a) : "l"(p));
    return a;
}

#define GP 36

// ======== GEMM epilogue ========
// mode: 0 plain, 1 relu+tf32round, 2 tf32round (after residual if any)
__device__ __forceinline__ void gemm_epilogue(float acc[4][4][4],
                                              const float* bias, const float* R,
                                              float* C, float* VT,
                                              int row0, int col0, int M, int mode,
                                              int wm, int wn, int gr, int lc) {
    bool vcols = (VT != nullptr) && (col0 >= 1024);
    #pragma unroll
    for (int mt = 0; mt < 4; mt++) {
        int r = row0 + wm * 64 + mt * 16 + gr;
        #pragma unroll
        for (int nt = 0; nt < 4; nt++) {
            int c = col0 + wn * 32 + nt * 8 + lc * 2;
            float b0 = bias[c], b1 = bias[c + 1];
            #pragma unroll
            for (int h2 = 0; h2 < 2; h2++) {
                int rr = r + h2 * 8;
                size_t off = (size_t)rr * M + c;
                float v0 = acc[mt][nt][h2 * 2 + 0] + b0;
                float v1 = acc[mt][nt][h2 * 2 + 1] + b1;
                if (R) { float2 rv = *(const float2*)(R + off); v0 += rv.x; v1 += rv.y; }
                if (mode == 1) {
                    v0 = tfround(fmaxf(v0, 0.f)); v1 = tfround(fmaxf(v1, 0.f));
                } else if (mode == 2) {
                    v0 = tfround(v0); v1 = tfround(v1);
                }
                if (!vcols) {
                    *(float2*)(C + off) = make_float2(v0, v1);
                } else {
                    int bbq = rr >> 11, s = rr & (SQ - 1);
                    int dc = c - 1024;
                    int hv = dc >> 6, d = dc & 63;
                    float* vp = VT + ((size_t)((bbq << 3) + hv) * 64 + d) * SQ + s;
                    vp[0]  = v0;
                    vp[SQ] = v1;
                }
            }
        }
    }
}

// ======== cp.async GEMM: 2-stage double buffer, 2 CTAs/SM ========
#define CPSTAGE 9216
#define GEMM_CP_SMEM (2 * CPSTAGE * 4)   // 73728 B -> 2 CTAs/SM

__global__ __launch_bounds__(256, 2) void gemm_cp(const float* __restrict__ A,
                                                  const float* __restrict__ Wt,
                                                  const float* __restrict__ bias,
                                                  const float* __restrict__ R,
                                                  float* __restrict__ C,
                                                  float* __restrict__ VT,
                                                  int K, int M, int mode) {
    extern __shared__ uint32_t sm[];
    uint32_t sb = smem_u32(sm);
    int t = threadIdx.x, lane = t & 31, wid = t >> 5;
    int wm = wid & 1, wn = wid >> 1;
    int gr = lane >> 2, lc = lane & 3;
    int row0 = blockIdx.y * 128, col0 = blockIdx.x * 128;
    const int NC = K >> 5;

    int half = t >> 7, li = t & 127;
    const float* src = half ? (Wt + (size_t)col0 * K) : (A + (size_t)row0 * K);

    float acc[4][4][4];
    #pragma unroll
    for (int i = 0; i < 4; i++)
        #pragma unroll
        for (int j = 0; j < 4; j++)
            #pragma unroll
            for (int k = 0; k < 4; k++) acc[i][j][k] = 0.f;

    auto issue = [&](int c, int st) {
        uint32_t dbase = sb + (st * CPSTAGE + half * 4608) * 4;
        const float* s0 = src + c * 32;
        #pragma unroll
        for (int j = 0; j < 8; j++) {
            int seg = j * 128 + li, r = seg >> 3, p = seg & 7;
            cpa16(dbase + (r * GP + p * 4) * 4, s0 + (size_t)r * K + p * 4);
        }
    };

    issue(0, 0); CP_COMMIT();

    for (int c = 0; c < NC; c++) {
        // WAR on buffer (c+1)&1 is protected by the sync at the END of iter c-1.
        if (c + 1 < NC) { issue(c + 1, (c + 1) & 1); CP_COMMIT(); CP_WAIT(1); }
        else            { CP_WAIT(0); }
        __syncthreads();                 // stage c visible to all warps

        const uint32_t* S = sm + (c & 1) * CPSTAGE;
        const uint32_t* Abase = S + (wm * 64 + gr) * GP + lc;
        const uint32_t* Bbase = S + 4608 + (wn * 32 + gr) * GP + lc;
        #pragma unroll
        for (int ks = 0; ks < 4; ks++) {
            uint32_t a[4][4], b[4][2];
            #pragma unroll
            for (int mt = 0; mt < 4; mt++) {
                const uint32_t* p = Abase + mt * 16 * GP + ks * 8;
                a[mt][0] = p[0]; a[mt][1] = p[8 * GP]; a[mt][2] = p[4]; a[mt][3] = p[8 * GP + 4];
            }
            #pragma unroll
            for (int nt = 0; nt < 4; nt++) {
                const uint32_t* p = Bbase + nt * 8 * GP + ks * 8;
                b[nt][0] = p[0]; b[nt][1] = p[4];
            }
            #pragma unroll
            for (int mt = 0; mt < 4; mt++)
                #pragma unroll
                for (int nt = 0; nt < 4; nt++)
                    mma8(acc[mt][nt], a[mt], b[nt]);
        }
        if (c + 1 < NC) __syncthreads(); // all readers of buf c&1 done before iter c+1 issues into it
    }

    gemm_epilogue(acc, bias, R, C, VT, row0, col0, M, mode, wm, wn, gr, lc);
}

// ---------------- flash attention v3 (R9-proven; R13 epilogue rounding) ----------------
#define AP 68
#define OQ 0
#define OKB 4352
#define OPS 13056
#define OST 17408
#define ATTN_SMEM ((OST + 192) * 4)

__global__ __launch_bounds__(128) void attn_mma(const float* __restrict__ qkv,
                                                const float* __restrict__ vt,
                                                float* __restrict__ out) {
    extern __shared__ uint32_t smu[];
    uint32_t sb = smem_u32(smu);
    int qt = gridDim.x - 1 - blockIdx.x;
    int bh = blockIdx.y, bb = bh >> 3, hh = bh & 7;
    int t = threadIdx.x, lane = t & 31, wid = t >> 5;
    int gr = lane >> 2, lc = lane & 3;
    int mrow = wid * 16 + gr;
    const size_t base = (size_t)bb * SQ * QKVW + hh * DK;
    const float* qb = qkv + base + (size_t)qt * 64 * QKVW;
    const float* vbase = vt + (size_t)bh * 64 * SQ;

    float* sm_m  = (float*)(smu + OST);
    float* sm_l  = sm_m + 64;
    float* sm_rs = sm_m + 128;
    uint32_t* Qs = smu + OQ;
    float*    Ps = (float*)(smu + OPS);

    #pragma unroll
    for (int i = 0; i < 8; i++) {
        int f = i * 128 + t, r = f >> 4, d4 = (f & 15) << 2;
        cpa16(sb + (OQ + r * AP + d4) * 4, qb + (size_t)r * QKVW + d4);
    }
    {
        const float* kb = qkv + base + 512;
        #pragma unroll
        for (int i = 0; i < 8; i++) {
            int f = i * 128 + t, r = f >> 4, d4 = (f & 15) << 2;
            cpa16(sb + (OKB + r * AP + d4) * 4, kb + (size_t)r * QKVW + d4);
        }
    }
    CP_COMMIT();

    if (lane < 16) { sm_m[wid * 16 + lane] = -1e30f; sm_l[wid * 16 + lane] = 0.f; }

    float co[8][4];
    #pragma unroll
    for (int i = 0; i < 8; i++)
        #pragma unroll
        for (int j = 0; j < 4; j++) co[i][j] = 0.f;

    for (int kt = 0; kt <= qt; kt++) {
        int cur = kt & 1;
        if (kt == 0) { CP_WAIT(0); __syncthreads(); }
        const uint32_t* Kb = smu + OKB + cur * 4352;

        float cs[8][4];
        #pragma unroll
        for (int i = 0; i < 8; i++)
            #pragma unroll
            for (int j = 0; j < 4; j++) cs[i][j] = 0.f;
        {
            const uint32_t* Abase = Qs + mrow * AP + lc;
            const uint32_t* Bbase = Kb + gr * AP + lc;
            #pragma unroll
            for (int ks = 0; ks < 8; ks++) {
                uint32_t a[4];
                const uint32_t* p = Abase + ks * 8;
                a[0] = p[0]; a[1] = p[8 * AP]; a[2] = p[4]; a[3] = p[8 * AP + 4];
                #pragma unroll
                for (int nt = 0; nt < 8; nt++) {
                    const uint32_t* q2 = Bbase + nt * 8 * AP + ks * 8;
                    uint32_t b[2] = {q2[0], q2[4]};
                    mma8(cs[nt], a, b);
                }
            }
        }
        #pragma unroll
        for (int nt = 0; nt < 8; nt++) {
            int c = nt * 8 + lc * 2;
            *(float2*)(Ps + mrow * AP + c)       = make_float2(cs[nt][0], cs[nt][1]);
            *(float2*)(Ps + (mrow + 8) * AP + c) = make_float2(cs[nt][2], cs[nt][3]);
        }
        __syncthreads();

        #pragma unroll
        for (int i = 0; i < 8; i++) {
            int f = i * 128 + t, d = f >> 4, k4 = (f & 15) << 2;
            cpa16(sb + (OKB + cur * 4352 + d * AP + k4) * 4,
                  vbase + (size_t)d * SQ + kt * 64 + k4);
        }
        CP_COMMIT();
        if (kt < qt) {
            const float* kb = qkv + base + 512 + (size_t)(kt + 1) * 64 * QKVW;
            #pragma unroll
            for (int i = 0; i < 8; i++) {
                int f = i * 128 + t, r = f >> 4, d4 = (f & 15) << 2;
                cpa16(sb + (OKB + (cur ^ 1) * 4352 + r * AP + d4) * 4,
                      kb + (size_t)r * QKVW + d4);
            }
            CP_COMMIT();
        }

        {
            int r = t >> 1, half = t & 1;
            int qrow = qt * 64 + r;
            int kbase0 = kt * 64 + half * 32;
            float* rowp = Ps + r * AP + half * 32;
            float vals[32];
            float mx = -1e30f;
            bool edge = (kt == qt);
            #pragma unroll
            for (int j = 0; j < 32; j += 4) {
                float4 v4 = *(const float4*)(rowp + j);
                float w0 = v4.x * 0.125f, w1 = v4.y * 0.125f;
                float w2 = v4.z * 0.125f, w3 = v4.w * 0.125f;
                if (edge) {
                    if (kbase0 + j + 0 > qrow) w0 = -1e30f;
                    if (kbase0 + j + 1 > qrow) w1 = -1e30f;
                    if (kbase0 + j + 2 > qrow) w2 = -1e30f;
                    if (kbase0 + j + 3 > qrow) w3 = -1e30f;
                }
                vals[j] = w0; vals[j+1] = w1; vals[j+2] = w2; vals[j+3] = w3;
                mx = fmaxf(mx, fmaxf(fmaxf(w0, w1), fmaxf(w2, w3)));
            }
            mx = fmaxf(mx, __shfl_xor_sync(0xffffffffu, mx, 1));
            float mo = sm_m[r];
            float mn = fmaxf(mo, mx);
            float rs = __expf(mo - mn);
            float ssum = 0.f;
            #pragma unroll
            for (int j = 0; j < 32; j += 4) {
                float p0 = __expf(vals[j]   - mn), p1 = __expf(vals[j+1] - mn);
                float p2 = __expf(vals[j+2] - mn), p3 = __expf(vals[j+3] - mn);
                ssum += (p0 + p1) + (p2 + p3);
                *(uint4*)(rowp + j) = make_uint4(f2tf(p0), f2tf(p1), f2tf(p2), f2tf(p3));
            }
            ssum += __shfl_xor_sync(0xffffffffu, ssum, 1);
            if (!half) { sm_l[r] = sm_l[r] * rs + ssum; sm_m[r] = mn; sm_rs[r] = rs; }
        }

        CP_WAIT(0);
        __syncthreads();

        {
            float rs0 = sm_rs[mrow], rs1 = sm_rs[mrow + 8];
            #pragma unroll
            for (int nt = 0; nt < 8; nt++) {
                co[nt][0] *= rs0; co[nt][1] *= rs0;
                co[nt][2] *= rs1; co[nt][3] *= rs1;
            }
            const uint32_t* Pb = (const uint32_t*)Ps + mrow * AP + lc;
            const uint32_t* Bbase = Kb + gr * AP + lc;
            #pragma unroll
            for (int ks = 0; ks < 8; ks++) {
                uint32_t a[4];
                const uint32_t* p = Pb + ks * 8;
                a[0] = p[0]; a[1] = p[8 * AP]; a[2] = p[4]; a[3] = p[8 * AP + 4];
                #pragma unroll
                for (int nt = 0; nt < 8; nt++) {
                    const uint32_t* q2 = Bbase + nt * 8 * AP + ks * 8;
                    uint32_t b[2] = {q2[0], q2[4]};
                    mma8(co[nt], a, b);
                }
            }
        }
    }

    float inv0 = 1.f / sm_l[mrow], inv1 = 1.f / sm_l[mrow + 8];
    float* ob = out + ((size_t)bb * SQ + (size_t)qt * 64) * DM + hh * DK;
    #pragma unroll
    for (int nt = 0; nt < 8; nt++) {
        int c = nt * 8 + lc * 2;
        *(float2*)(ob + (size_t)mrow * DM + c) =
            make_float2(tfround(co[nt][0] * inv0), tfround(co[nt][1] * inv0));
        *(float2*)(ob + (size_t)(mrow + 8) * DM + c) =
            make_float2(tfround(co[nt][2] * inv1), tfround(co[nt][3] * inv1));
    }
}

// ---------------- weight transposes (write tf32-rounded) ----------------
__global__ __launch_bounds__(256) void transpose_k(const float* __restrict__ in,
                                                   float* __restrict__ out,
                                                   int R, int C,
                                                   size_t in_z, size_t out_z) {
    __shared__ float tbuf[32][33];
    in  += blockIdx.z * in_z;
    out += blockIdx.z * out_z;
    int c0 = blockIdx.x * 32, r0 = blockIdx.y * 32;
    #pragma unroll
    for (int i = 0; i < 32; i += 8)
        tbuf[threadIdx.y + i][threadIdx.x] = in[(size_t)(r0 + threadIdx.y + i) * C + c0 + threadIdx.x];
    __syncthreads();
    #pragma unroll
    for (int i = 0; i < 32; i += 8)
        out[(size_t)(c0 + threadIdx.y + i) * R + r0 + threadIdx.x] =
            tfround(tbuf[threadIdx.x][threadIdx.y + i]);
}

__global__ __launch_bounds__(256) void transpose_qkv(const float* __restrict__ wq,
                                                     const float* __restrict__ wk,
                                                     const float* __restrict__ wv,
                                                     float* __restrict__ outT) {
    __shared__ float tbuf[32][33];
    int z = blockIdx.z, l = z / 3, w = z % 3;
    const float* in = (w == 0 ? wq : w == 1 ? wk : wv) + (size_t)l * DM * DM;
    float* out = outT + (size_t)l * QKVW * DM + (size_t)w * DM * DM;
    int c0 = blockIdx.x * 32, r0 = blockIdx.y * 32;
    #pragma unroll
    for (int i = 0; i < 32; i += 8)
        tbuf[threadIdx.y + i][threadIdx.x] = in[(size_t)(r0 + threadIdx.y + i) * DM + c0 + threadIdx.x];
    __syncthreads();
    #pragma unroll
    for (int i = 0; i < 32; i += 8)
        out[(size_t)(c0 + threadIdx.y + i) * DM + r0 + threadIdx.x] =
            tfround(tbuf[threadIdx.x][threadIdx.y + i]);
}

__global__ __launch_bounds__(256) void biaspack_kernel(const float* __restrict__ bq,
                                                       const float* __restrict__ bk,
                                                       const float* __restrict__ bv,
                                                       float* __restrict__ dst) {
    int idx = blockIdx.x * 256 + threadIdx.x;
    if (idx >= NL * QKVW) return;
    int l = idx / QKVW, j = idx % QKVW;
    float v;
    if (j < 512)       v = bq[l * 512 + j];
    else if (j < 1024) v = bk[l * 512 + j - 512];
    else               v = bv[l * 512 + j - 1024];
    dst[idx] = v;
}

// ---------------- fused embed + layer-0 ln1 ----------------
__global__ __launch_bounds__(256) void embed_ln(const int* __restrict__ ids,
                                                const float* __restrict__ emb,
                                                const float* __restrict__ w,
                                                const float* __restrict__ bias,
                                                float* __restrict__ x,
                                                float* __restrict__ y) {
    __shared__ float sred[16];
    int row = blockIdx.x, t = threadIdx.x;
    int s = row & (SQ - 1);
    int tok = ids[row];
    float v0, v1;
    {
        int d = t, i2 = d & ~1;
        float div = expf(-(float)i2 * (9.210340371976184f / 512.0f));
        float ang = (float)s * div;
        float pe = (d & 1) ? cosf(ang) : sinf(ang);
        v0 = emb[(size_t)tok * DM + d] + pe;
    }
    {
        int d = t + 256, i2 = d & ~1;
        float div = expf(-(float)i2 * (9.210340371976184f / 512.0f));
        float ang = (float)s * div;
        float pe = (d & 1) ? cosf(ang) : sinf(ang);
        v1 = emb[(size_t)tok * DM + d] + pe;
    }
    float* xr = x + (size_t)row * DM;
    xr[t] = v0;
    xr[t + 256] = v1;
    float ssum = v0 + v1;
    #pragma unroll
    for (int off = 16; off; off >>= 1) ssum += __shfl_xor_sync(0xffffffffu, ssum, off);
    if ((t & 31) == 0) sred[t >> 5] = ssum;
    __syncthreads();
    float tot = 0.f;
    #pragma unroll
    for (int i = 0; i < 8; i++) tot += sred[i];
    float mu = tot * (1.0f / DM);
    float d0 = v0 - mu, d1 = v1 - mu;
    float s2 = d0 * d0 + d1 * d1;
    #pragma unroll
    for (int off = 16; off; off >>= 1) s2 += __shfl_xor_sync(0xffffffffu, s2, off);
    if ((t & 31) == 0) sred[8 + (t >> 5)] = s2;
    __syncthreads();
    float tot2 = 0.f;
    #pragma unroll
    for (int i = 0; i < 8; i++) tot2 += sred[8 + i];
    float rstd = rsqrtf(tot2 * (1.0f / DM) + 1e-5f);
    float* yr = y + (size_t)row * DM;
    yr[t]       = tfround(d0 * rstd * w[t]       + bias[t]);
    yr[t + 256] = tfround(d1 * rstd * w[t + 256] + bias[t + 256]);
}

// ---------------- layernorm: 2 rows / 512-thread block ----------------
__global__ __launch_bounds__(512) void ln_kernel(const float* __restrict__ x,
                                                 const float* __restrict__ w,
                                                 const float* __restrict__ bias,
                                                 float* __restrict__ y) {
    __shared__ float sred[32];
    int half = threadIdx.x >> 8;
    int t = threadIdx.x & 255;
    int row = blockIdx.x * 2 + half;
    float* sr = sred + half * 16;
    const float* xr = x + (size_t)row * DM;
    float v0 = xr[t];
    float v1 = xr[t + 256];
    float s = v0 + v1;
    #pragma unroll
    for (int off = 16; off; off >>= 1) s += __shfl_xor_sync(0xffffffffu, s, off);
    if ((t & 31) == 0) sr[t >> 5] = s;
    __syncthreads();
    float tot = 0.f;
    #pragma unroll
    for (int i = 0; i < 8; i++) tot += sr[i];
    float mu = tot * (1.0f / DM);
    float d0 = v0 - mu, d1 = v1 - mu;
    float s2 = d0 * d0 + d1 * d1;
    #pragma unroll
    for (int off = 16; off; off >>= 1) s2 += __shfl_xor_sync(0xffffffffu, s2, off);
    if ((t & 31) == 0) sr[8 + (t >> 5)] = s2;
    __syncthreads();
    float tot2 = 0.f;
    #pragma unroll
    for (int i = 0; i < 8; i++) tot2 += sr[8 + i];
    float rstd = rsqrtf(tot2 * (1.0f / DM) + 1e-5f);
    float* yr = y + (size_t)row * DM;
    yr[t]       = tfround(d0 * rstd * w[t]       + bias[t]);
    yr[t + 256] = tfround(d1 * rstd * w[t + 256] + bias[t + 256]);
}

// ---------------- host ----------------
static void run_gemm_cp(const float* A, const float* Wt, const float* bias, const float* R,
                        float* C, float* VT, int K, int M, int mode) {
    gemm_cp<<<dim3(M / 128, NTOK / 128), 256, GEMM_CP_SMEM>>>(A, Wt, bias, R, C, VT, K, M, mode);
}

extern "C" void kernel_launch(void* const* d_in, const int* in_sizes, int n_in,
                              void* d_out, int out_size) {
    (void)in_sizes; (void)n_in; (void)out_size;
    const int*   ids  = (const int*)  d_in[0];
    const float* emb  = (const float*)d_in[1];
    const float* wq   = (const float*)d_in[2];
    const float* bq   = (const float*)d_in[3];
    const float* wk   = (const float*)d_in[4];
    const float* bk   = (const float*)d_in[5];
    const float* wv   = (const float*)d_in[6];
    const float* bv   = (const float*)d_in[7];
    const float* wo   = (const float*)d_in[8];
    const float* bo   = (const float*)d_in[9];
    const float* ln1w = (const float*)d_in[10];
    const float* ln1b = (const float*)d_in[11];
    const float* ln2w = (const float*)d_in[12];
    const float* ln2b = (const float*)d_in[13];
    const float* w1   = (const float*)d_in[14];
    const float* b1   = (const float*)d_in[15];
    const float* w2   = (const float*)d_in[16];
    const float* b2   = (const float*)d_in[17];
    const float* outw = (const float*)d_in[18];
    const float* outb = (const float*)d_in[19];

    float *x, *h, *qkv, *ff, *vt, *wqkvT, *woT, *w1T, *w2T, *outwT, *bqkv;
    cudaGetSymbolAddress((void**)&x,     g_x);
    cudaGetSymbolAddress((void**)&h,     g_h);
    cudaGetSymbolAddress((void**)&qkv,   g_qkv);
    cudaGetSymbolAddress((void**)&ff,    g_ff);
    cudaGetSymbolAddress((void**)&vt,    g_vt);
    cudaGetSymbolAddress((void**)&wqkvT, g_wqkvT);
    cudaGetSymbolAddress((void**)&woT,   g_woT);
    cudaGetSymbolAddress((void**)&w1T,   g_w1T);
    cudaGetSymbolAddress((void**)&w2T,   g_w2T);
    cudaGetSymbolAddress((void**)&outwT, g_outwT);
    cudaGetSymbolAddress((void**)&bqkv,  g_bqkv);

    cudaFuncSetAttribute(gemm_cp,  cudaFuncAttributeMaxDynamicSharedMemorySize, GEMM_CP_SMEM);
    cudaFuncSetAttribute(attn_mma, cudaFuncAttributeMaxDynamicSharedMemorySize, ATTN_SMEM);

    dim3 tb(32, 8);

    embed_ln<<<NTOK, 256>>>(ids, emb, ln1w, ln1b, x, h);                       // 1
    transpose_qkv<<<dim3(16, 16, 3 * NL), tb>>>(wq, wk, wv, wqkvT);            // 2
    biaspack_kernel<<<(NL * QKVW + 255) / 256, 256>>>(bq, bk, bv, bqkv);       // 3
    run_gemm_cp(h, wqkvT, bqkv, nullptr, qkv, vt, DM, QKVW, 2);                // 4
    transpose_k<<<dim3(16, 16, NL), tb>>>(wo, woT, DM, DM, (size_t)DM*DM, (size_t)DM*DM);
    transpose_k<<<dim3(DFF/32, 16, NL), tb>>>(w1, w1T, DM, DFF, (size_t)DM*DFF, (size_t)DM*DFF);
    transpose_k<<<dim3(16, DFF/32, NL), tb>>>(w2, w2T, DFF, DM, (size_t)DM*DFF, (size_t)DM*DFF);
    transpose_k<<<dim3(NV/32, 16, 1),   tb>>>(outw, outwT, DM, NV, 0, 0);

    for (int l = 0; l < NL; l++) {
        size_t offD = (size_t)l * DM;
        size_t offF = (size_t)l * DFF;

        if (l > 0) {
            ln_kernel<<<NTOK / 2, 512>>>(x, ln1w + offD, ln1b + offD, h);
            run_gemm_cp(h, wqkvT + (size_t)l * QKVW * DM, bqkv + (size_t)l * QKVW, nullptr,
                        qkv, vt, DM, QKVW, 2);
        }
        attn_mma<<<dim3(SQ / 64, NB * NH), 128, ATTN_SMEM>>>(qkv, vt, h);
        run_gemm_cp(h, woT + (size_t)l * DM * DM, bo + offD, nullptr, x, nullptr, DM, DM, 0);
        ln_kernel<<<NTOK / 2, 512>>>(x, ln2w + offD, ln2b + offD, h);
        run_gemm_cp(h, w1T + (size_t)l * DM * DFF, b1 + offF, nullptr, ff, nullptr, DM, DFF, 1);
        run_gemm_cp(ff, w2T + (size_t)l * DM * DFF, b2 + offD, x /*residual*/, x, nullptr,
                    DFF, DM, (l == NL - 1) ? 2 : 0);
    }

    run_gemm_cp(x, outwT, outb, nullptr, (float*)d_out, nullptr, DM, NV, 0);
}

// round 16
// speedup vs baseline: 1.6249x; 1.5078x over previous
#include <cuda_runtime.h>
#include <math.h>
#include <stdint.h>

#define NB 2
#define SQ 2048
#define NTOK 4096
#define DM 512
#define NH 8
#define DK 64
#define NL 6
#define DFF 2048
#define NV 1024
#define QKVW 1536

// ---------------- scratch ----------------
__device__ float g_x   [NTOK * DM];
__device__ float g_h   [NTOK * DM];
__device__ float g_qkv [NTOK * QKVW];
__device__ float g_ff  [NTOK * DFF];
__device__ float g_vt  [16 * 64 * SQ];
__device__ float g_wqkvT[NL * QKVW * DM];
__device__ float g_woT  [NL * DM * DM];
__device__ float g_w1T  [NL * DFF * DM];
__device__ float g_w2T  [NL * DM * DFF];
__device__ float g_outwT[NV * DM];
__device__ float g_bqkv [NL * QKVW];

// ---------------- helpers ----------------
__device__ __forceinline__ uint32_t f2tf(float f) {
    uint32_t r;
    asm("cvt.rna.tf32.f32 %0, %1;" : "=r"(r) : "f"(f));
    return r;
}
__device__ __forceinline__ float tfround(float f) { return __uint_as_float(f2tf(f)); }
__device__ __forceinline__ void mma8(float* c, const uint32_t* a, const uint32_t* b) {
    asm volatile(
        "mma.sync.aligned.m16n8k8.row.col.f32.tf32.tf32.f32 "
        "{%0,%1,%2,%3}, {%4,%5,%6,%7}, {%8,%9}, {%0,%1,%2,%3};\n"
        : "+f"(c[0]), "+f"(c[1]), "+f"(c[2]), "+f"(c[3])
        : "r"(a[0]), "r"(a[1]), "r"(a[2]), "r"(a[3]), "r"(b[0]), "r"(b[1]));
}
__device__ __forceinline__ void cpa16(uint32_t dst, const void* src) {
    asm volatile("cp.async.cg.shared.global [%0], [%1], 16;" :: "r"(dst), "l"(src));
}
#define CP_COMMIT() asm volatile("cp.async.commit_group;" ::: "memory")
#define CP_WAIT(n)  asm volatile("cp.async.wait_group %0;" :: "n"(n) : "memory")
__device__ __forceinline__ uint32_t smem_u32(const void* p) {
    uint32_t a;
    asm("{ .reg .u64 t; cvta.to.shared.u64 t, %1; cvt.u32.u64 %0, t; }" : "=r"(a) : "l"(p));
    return a;
}

#define GP 36

// ======== GEMM epilogue ========
// mode: 0 plain, 1 relu+tf32round, 2 tf32round (after residual if any)
__device__ __forceinline__ void gemm_epilogue(float acc[4][4][4],
                                              const float* bias, const float* R,
                                              float* C, float* VT,
                                              int row0, int col0, int M, int mode,
                                              int wm, int wn, int gr, int lc) {
    bool vcols = (VT != nullptr) && (col0 >= 1024);
    #pragma unroll
    for (int mt = 0; mt < 4; mt++) {
        int r = row0 + wm * 64 + mt * 16 + gr;
        #pragma unroll
        for (int nt = 0; nt < 4; nt++) {
            int c = col0 + wn * 32 + nt * 8 + lc * 2;
            float b0 = bias[c], b1 = bias[c + 1];
            #pragma unroll
            for (int h2 = 0; h2 < 2; h2++) {
                int rr = r + h2 * 8;
                size_t off = (size_t)rr * M + c;
                float v0 = acc[mt][nt][h2 * 2 + 0] + b0;
                float v1 = acc[mt][nt][h2 * 2 + 1] + b1;
                if (R) { float2 rv = *(const float2*)(R + off); v0 += rv.x; v1 += rv.y; }
                if (mode == 1) {
                    v0 = tfround(fmaxf(v0, 0.f)); v1 = tfround(fmaxf(v1, 0.f));
                } else if (mode == 2) {
                    v0 = tfround(v0); v1 = tfround(v1);
                }
                if (!vcols) {
                    *(float2*)(C + off) = make_float2(v0, v1);
                } else {
                    int bbq = rr >> 11, s = rr & (SQ - 1);
                    int dc = c - 1024;
                    int hv = dc >> 6, d = dc & 63;
                    float* vp = VT + ((size_t)((bbq << 3) + hv) * 64 + d) * SQ + s;
                    vp[0]  = v0;
                    vp[SQ] = v1;
                }
            }
        }
    }
}

// ======== cp.async GEMM: 3-stage pipeline, 128 regs -> 2 CTAs/SM ========
#define CPSTAGE 9216
#define GEMM_CP_SMEM (3 * CPSTAGE * 4)   // 110592 B; x2 CTAs = 221KB <= 228KB

__global__ __launch_bounds__(256, 2) void gemm_cp(const float* __restrict__ A,
                                                  const float* __restrict__ Wt,
                                                  const float* __restrict__ bias,
                                                  const float* __restrict__ R,
                                                  float* __restrict__ C,
                                                  float* __restrict__ VT,
                                                  int K, int M, int mode) {
    extern __shared__ uint32_t sm[];
    uint32_t sb = smem_u32(sm);
    int t = threadIdx.x, lane = t & 31, wid = t >> 5;
    int wm = wid & 1, wn = wid >> 1;
    int gr = lane >> 2, lc = lane & 3;
    int row0 = blockIdx.y * 128, col0 = blockIdx.x * 128;
    const int NC = K >> 5;

    int half = t >> 7, li = t & 127;
    const float* src = half ? (Wt + (size_t)col0 * K) : (A + (size_t)row0 * K);

    float acc[4][4][4];
    #pragma unroll
    for (int i = 0; i < 4; i++)
        #pragma unroll
        for (int j = 0; j < 4; j++)
            #pragma unroll
            for (int k = 0; k < 4; k++) acc[i][j][k] = 0.f;

    auto issue = [&](int c, int st) {
        uint32_t dbase = sb + (st * CPSTAGE + half * 4608) * 4;
        const float* s0 = src + c * 32;
        #pragma unroll
        for (int j = 0; j < 8; j++) {
            int seg = j * 128 + li, r = seg >> 3, p = seg & 7;
            cpa16(dbase + (r * GP + p * 4) * 4, s0 + (size_t)r * K + p * 4);
        }
    };

    issue(0, 0); CP_COMMIT();
    if (NC > 1) { issue(1, 1); CP_COMMIT(); }

    for (int c = 0; c < NC; c++) {
        if (c + 1 < NC) { CP_WAIT(1); } else { CP_WAIT(0); }
        __syncthreads();                 // stage c visible; also fences iter c-1 reads of stage (c+2)%3
        if (c + 2 < NC) { issue(c + 2, (c + 2) % 3); CP_COMMIT(); }

        const uint32_t* S = sm + (c % 3) * CPSTAGE;
        const uint32_t* Abase = S + (wm * 64 + gr) * GP + lc;
        const uint32_t* Bbase = S + 4608 + (wn * 32 + gr) * GP + lc;
        #pragma unroll
        for (int ks = 0; ks < 4; ks++) {
            uint32_t a[4][4], b[4][2];
            #pragma unroll
            for (int mt = 0; mt < 4; mt++) {
                const uint32_t* p = Abase + mt * 16 * GP + ks * 8;
                a[mt][0] = p[0]; a[mt][1] = p[8 * GP]; a[mt][2] = p[4]; a[mt][3] = p[8 * GP + 4];
            }
            #pragma unroll
            for (int nt = 0; nt < 4; nt++) {
                const uint32_t* p = Bbase + nt * 8 * GP + ks * 8;
                b[nt][0] = p[0]; b[nt][1] = p[4];
            }
            #pragma unroll
            for (int mt = 0; mt < 4; mt++)
                #pragma unroll
                for (int nt = 0; nt < 4; nt++)
                    mma8(acc[mt][nt], a[mt], b[nt]);
        }
    }

    gemm_epilogue(acc, bias, R, C, VT, row0, col0, M, mode, wm, wn, gr, lc);
}

// ---------------- flash attention v3 (R9-proven; R13 epilogue rounding) ----------------
#define AP 68
#define OQ 0
#define OKB 4352
#define OPS 13056
#define OST 17408
#define ATTN_SMEM ((OST + 192) * 4)

__global__ __launch_bounds__(128) void attn_mma(const float* __restrict__ qkv,
                                                const float* __restrict__ vt,
                                                float* __restrict__ out) {
    extern __shared__ uint32_t smu[];
    uint32_t sb = smem_u32(smu);
    int qt = gridDim.x - 1 - blockIdx.x;
    int bh = blockIdx.y, bb = bh >> 3, hh = bh & 7;
    int t = threadIdx.x, lane = t & 31, wid = t >> 5;
    int gr = lane >> 2, lc = lane & 3;
    int mrow = wid * 16 + gr;
    const size_t base = (size_t)bb * SQ * QKVW + hh * DK;
    const float* qb = qkv + base + (size_t)qt * 64 * QKVW;
    const float* vbase = vt + (size_t)bh * 64 * SQ;

    float* sm_m  = (float*)(smu + OST);
    float* sm_l  = sm_m + 64;
    float* sm_rs = sm_m + 128;
    uint32_t* Qs = smu + OQ;
    float*    Ps = (float*)(smu + OPS);

    #pragma unroll
    for (int i = 0; i < 8; i++) {
        int f = i * 128 + t, r = f >> 4, d4 = (f & 15) << 2;
        cpa16(sb + (OQ + r * AP + d4) * 4, qb + (size_t)r * QKVW + d4);
    }
    {
        const float* kb = qkv + base + 512;
        #pragma unroll
        for (int i = 0; i < 8; i++) {
            int f = i * 128 + t, r = f >> 4, d4 = (f & 15) << 2;
            cpa16(sb + (OKB + r * AP + d4) * 4, kb + (size_t)r * QKVW + d4);
        }
    }
    CP_COMMIT();

    if (lane < 16) { sm_m[wid * 16 + lane] = -1e30f; sm_l[wid * 16 + lane] = 0.f; }

    float co[8][4];
    #pragma unroll
    for (int i = 0; i < 8; i++)
        #pragma unroll
        for (int j = 0; j < 4; j++) co[i][j] = 0.f;

    for (int kt = 0; kt <= qt; kt++) {
        int cur = kt & 1;
        if (kt == 0) { CP_WAIT(0); __syncthreads(); }
        const uint32_t* Kb = smu + OKB + cur * 4352;

        float cs[8][4];
        #pragma unroll
        for (int i = 0; i < 8; i++)
            #pragma unroll
            for (int j = 0; j < 4; j++) cs[i][j] = 0.f;
        {
            const uint32_t* Abase = Qs + mrow * AP + lc;
            const uint32_t* Bbase = Kb + gr * AP + lc;
            #pragma unroll
            for (int ks = 0; ks < 8; ks++) {
                uint32_t a[4];
                const uint32_t* p = Abase + ks * 8;
                a[0] = p[0]; a[1] = p[8 * AP]; a[2] = p[4]; a[3] = p[8 * AP + 4];
                #pragma unroll
                for (int nt = 0; nt < 8; nt++) {
                    const uint32_t* q2 = Bbase + nt * 8 * AP + ks * 8;
                    uint32_t b[2] = {q2[0], q2[4]};
                    mma8(cs[nt], a, b);
                }
            }
        }
        #pragma unroll
        for (int nt = 0; nt < 8; nt++) {
            int c = nt * 8 + lc * 2;
            *(float2*)(Ps + mrow * AP + c)       = make_float2(cs[nt][0], cs[nt][1]);
            *(float2*)(Ps + (mrow + 8) * AP + c) = make_float2(cs[nt][2], cs[nt][3]);
        }
        __syncthreads();

        #pragma unroll
        for (int i = 0; i < 8; i++) {
            int f = i * 128 + t, d = f >> 4, k4 = (f & 15) << 2;
            cpa16(sb + (OKB + cur * 4352 + d * AP + k4) * 4,
                  vbase + (size_t)d * SQ + kt * 64 + k4);
        }
        CP_COMMIT();
        if (kt < qt) {
            const float* kb = qkv + base + 512 + (size_t)(kt + 1) * 64 * QKVW;
            #pragma unroll
            for (int i = 0; i < 8; i++) {
                int f = i * 128 + t, r = f >> 4, d4 = (f & 15) << 2;
                cpa16(sb + (OKB + (cur ^ 1) * 4352 + r * AP + d4) * 4,
                      kb + (size_t)r * QKVW + d4);
            }
            CP_COMMIT();
        }

        {
            int r = t >> 1, half = t & 1;
            int qrow = qt * 64 + r;
            int kbase0 = kt * 64 + half * 32;
            float* rowp = Ps + r * AP + half * 32;
            float vals[32];
            float mx = -1e30f;
            bool edge = (kt == qt);
            #pragma unroll
            for (int j = 0; j < 32; j += 4) {
                float4 v4 = *(const float4*)(rowp + j);
                float w0 = v4.x * 0.125f, w1 = v4.y * 0.125f;
                float w2 = v4.z * 0.125f, w3 = v4.w * 0.125f;
                if (edge) {
                    if (kbase0 + j + 0 > qrow) w0 = -1e30f;
                    if (kbase0 + j + 1 > qrow) w1 = -1e30f;
                    if (kbase0 + j + 2 > qrow) w2 = -1e30f;
                    if (kbase0 + j + 3 > qrow) w3 = -1e30f;
                }
                vals[j] = w0; vals[j+1] = w1; vals[j+2] = w2; vals[j+3] = w3;
                mx = fmaxf(mx, fmaxf(fmaxf(w0, w1), fmaxf(w2, w3)));
            }
            mx = fmaxf(mx, __shfl_xor_sync(0xffffffffu, mx, 1));
            float mo = sm_m[r];
            float mn = fmaxf(mo, mx);
            float rs = __expf(mo - mn);
            float ssum = 0.f;
            #pragma unroll
            for (int j = 0; j < 32; j += 4) {
                float p0 = __expf(vals[j]   - mn), p1 = __expf(vals[j+1] - mn);
                float p2 = __expf(vals[j+2] - mn), p3 = __expf(vals[j+3] - mn);
                ssum += (p0 + p1) + (p2 + p3);
                *(uint4*)(rowp + j) = make_uint4(f2tf(p0), f2tf(p1), f2tf(p2), f2tf(p3));
            }
            ssum += __shfl_xor_sync(0xffffffffu, ssum, 1);
            if (!half) { sm_l[r] = sm_l[r] * rs + ssum; sm_m[r] = mn; sm_rs[r] = rs; }
        }

        CP_WAIT(0);
        __syncthreads();

        {
            float rs0 = sm_rs[mrow], rs1 = sm_rs[mrow + 8];
            #pragma unroll
            for (int nt = 0; nt < 8; nt++) {
                co[nt][0] *= rs0; co[nt][1] *= rs0;
                co[nt][2] *= rs1; co[nt][3] *= rs1;
            }
            const uint32_t* Pb = (const uint32_t*)Ps + mrow * AP + lc;
            const uint32_t* Bbase = Kb + gr * AP + lc;
            #pragma unroll
            for (int ks = 0; ks < 8; ks++) {
                uint32_t a[4];
                const uint32_t* p = Pb + ks * 8;
                a[0] = p[0]; a[1] = p[8 * AP]; a[2] = p[4]; a[3] = p[8 * AP + 4];
                #pragma unroll
                for (int nt = 0; nt < 8; nt++) {
                    const uint32_t* q2 = Bbase + nt * 8 * AP + ks * 8;
                    uint32_t b[2] = {q2[0], q2[4]};
                    mma8(co[nt], a, b);
                }
            }
        }
    }

    float inv0 = 1.f / sm_l[mrow], inv1 = 1.f / sm_l[mrow + 8];
    float* ob = out + ((size_t)bb * SQ + (size_t)qt * 64) * DM + hh * DK;
    #pragma unroll
    for (int nt = 0; nt < 8; nt++) {
        int c = nt * 8 + lc * 2;
        *(float2*)(ob + (size_t)mrow * DM + c) =
            make_float2(tfround(co[nt][0] * inv0), tfround(co[nt][1] * inv0));
        *(float2*)(ob + (size_t)(mrow + 8) * DM + c) =
            make_float2(tfround(co[nt][2] * inv1), tfround(co[nt][3] * inv1));
    }
}

// ---------------- weight transposes (write tf32-rounded) ----------------
__global__ __launch_bounds__(256) void transpose_k(const float* __restrict__ in,
                                                   float* __restrict__ out,
                                                   int R, int C,
                                                   size_t in_z, size_t out_z) {
    __shared__ float tbuf[32][33];
    in  += blockIdx.z * in_z;
    out += blockIdx.z * out_z;
    int c0 = blockIdx.x * 32, r0 = blockIdx.y * 32;
    #pragma unroll
    for (int i = 0; i < 32; i += 8)
        tbuf[threadIdx.y + i][threadIdx.x] = in[(size_t)(r0 + threadIdx.y + i) * C + c0 + threadIdx.x];
    __syncthreads();
    #pragma unroll
    for (int i = 0; i < 32; i += 8)
        out[(size_t)(c0 + threadIdx.y + i) * R + r0 + threadIdx.x] =
            tfround(tbuf[threadIdx.x][threadIdx.y + i]);
}

__global__ __launch_bounds__(256) void transpose_qkv(const float* __restrict__ wq,
                                                     const float* __restrict__ wk,
                                                     const float* __restrict__ wv,
                                                     float* __restrict__ outT) {
    __shared__ float tbuf[32][33];
    int z = blockIdx.z, l = z / 3, w = z % 3;
    const float* in = (w == 0 ? wq : w == 1 ? wk : wv) + (size_t)l * DM * DM;
    float* out = outT + (size_t)l * QKVW * DM + (size_t)w * DM * DM;
    int c0 = blockIdx.x * 32, r0 = blockIdx.y * 32;
    #pragma unroll
    for (int i = 0; i < 32; i += 8)
        tbuf[threadIdx.y + i][threadIdx.x] = in[(size_t)(r0 + threadIdx.y + i) * DM + c0 + threadIdx.x];
    __syncthreads();
    #pragma unroll
    for (int i = 0; i < 32; i += 8)
        out[(size_t)(c0 + threadIdx.y + i) * DM + r0 + threadIdx.x] =
            tfround(tbuf[threadIdx.x][threadIdx.y + i]);
}

__global__ __launch_bounds__(256) void biaspack_kernel(const float* __restrict__ bq,
                                                       const float* __restrict__ bk,
                                                       const float* __restrict__ bv,
                                                       float* __restrict__ dst) {
    int idx = blockIdx.x * 256 + threadIdx.x;
    if (idx >= NL * QKVW) return;
    int l = idx / QKVW, j = idx % QKVW;
    float v;
    if (j < 512)       v = bq[l * 512 + j];
    else if (j < 1024) v = bk[l * 512 + j - 512];
    else               v = bv[l * 512 + j - 1024];
    dst[idx] = v;
}

// ---------------- fused embed + layer-0 ln1 ----------------
__global__ __launch_bounds__(256) void embed_ln(const int* __restrict__ ids,
                                                const float* __restrict__ emb,
                                                const float* __restrict__ w,
                                                const float* __restrict__ bias,
                                                float* __restrict__ x,
                                                float* __restrict__ y) {
    __shared__ float sred[16];
    int row = blockIdx.x, t = threadIdx.x;
    int s = row & (SQ - 1);
    int tok = ids[row];
    float v0, v1;
    {
        int d = t, i2 = d & ~1;
        float div = expf(-(float)i2 * (9.210340371976184f / 512.0f));
        float ang = (float)s * div;
        float pe = (d & 1) ? cosf(ang) : sinf(ang);
        v0 = emb[(size_t)tok * DM + d] + pe;
    }
    {
        int d = t + 256, i2 = d & ~1;
        float div = expf(-(float)i2 * (9.210340371976184f / 512.0f));
        float ang = (float)s * div;
        float pe = (d & 1) ? cosf(ang) : sinf(ang);
        v1 = emb[(size_t)tok * DM + d] + pe;
    }
    float* xr = x + (size_t)row * DM;
    xr[t] = v0;
    xr[t + 256] = v1;
    float ssum = v0 + v1;
    #pragma unroll
    for (int off = 16; off; off >>= 1) ssum += __shfl_xor_sync(0xffffffffu, ssum, off);
    if ((t & 31) == 0) sred[t >> 5] = ssum;
    __syncthreads();
    float tot = 0.f;
    #pragma unroll
    for (int i = 0; i < 8; i++) tot += sred[i];
    float mu = tot * (1.0f / DM);
    float d0 = v0 - mu, d1 = v1 - mu;
    float s2 = d0 * d0 + d1 * d1;
    #pragma unroll
    for (int off = 16; off; off >>= 1) s2 += __shfl_xor_sync(0xffffffffu, s2, off);
    if ((t & 31) == 0) sred[8 + (t >> 5)] = s2;
    __syncthreads();
    float tot2 = 0.f;
    #pragma unroll
    for (int i = 0; i < 8; i++) tot2 += sred[8 + i];
    float rstd = rsqrtf(tot2 * (1.0f / DM) + 1e-5f);
    float* yr = y + (size_t)row * DM;
    yr[t]       = tfround(d0 * rstd * w[t]       + bias[t]);
    yr[t + 256] = tfround(d1 * rstd * w[t + 256] + bias[t + 256]);
}

// ---------------- layernorm: 2 rows / 512-thread block ----------------
__global__ __launch_bounds__(512) void ln_kernel(const float* __restrict__ x,
                                                 const float* __restrict__ w,
                                                 const float* __restrict__ bias,
                                                 float* __restrict__ y) {
    __shared__ float sred[32];
    int half = threadIdx.x >> 8;
    int t = threadIdx.x & 255;
    int row = blockIdx.x * 2 + half;
    float* sr = sred + half * 16;
    const float* xr = x + (size_t)row * DM;
    float v0 = xr[t];
    float v1 = xr[t + 256];
    float s = v0 + v1;
    #pragma unroll
    for (int off = 16; off; off >>= 1) s += __shfl_xor_sync(0xffffffffu, s, off);
    if ((t & 31) == 0) sr[t >> 5] = s;
    __syncthreads();
    float tot = 0.f;
    #pragma unroll
    for (int i = 0; i < 8; i++) tot += sr[i];
    float mu = tot * (1.0f / DM);
    float d0 = v0 - mu, d1 = v1 - mu;
    float s2 = d0 * d0 + d1 * d1;
    #pragma unroll
    for (int off = 16; off; off >>= 1) s2 += __shfl_xor_sync(0xffffffffu, s2, off);
    if ((t & 31) == 0) sr[8 + (t >> 5)] = s2;
    __syncthreads();
    float tot2 = 0.f;
    #pragma unroll
    for (int i = 0; i < 8; i++) tot2 += sr[8 + i];
    float rstd = rsqrtf(tot2 * (1.0f / DM) + 1e-5f);
    float* yr = y + (size_t)row * DM;
    yr[t]       = tfround(d0 * rstd * w[t]       + bias[t]);
    yr[t + 256] = tfround(d1 * rstd * w[t + 256] + bias[t + 256]);
}

// ---------------- host ----------------
static void run_gemm_cp(const float* A, const float* Wt, const float* bias, const float* R,
                        float* C, float* VT, int K, int M, int mode) {
    gemm_cp<<<dim3(M / 128, NTOK / 128), 256, GEMM_CP_SMEM>>>(A, Wt, bias, R, C, VT, K, M, mode);
}

extern "C" void kernel_launch(void* const* d_in, const int* in_sizes, int n_in,
                              void* d_out, int out_size) {
    (void)in_sizes; (void)n_in; (void)out_size;
    const int*   ids  = (const int*)  d_in[0];
    const float* emb  = (const float*)d_in[1];
    const float* wq   = (const float*)d_in[2];
    const float* bq   = (const float*)d_in[3];
    const float* wk   = (const float*)d_in[4];
    const float* bk   = (const float*)d_in[5];
    const float* wv   = (const float*)d_in[6];
    const float* bv   = (const float*)d_in[7];
    const float* wo   = (const float*)d_in[8];
    const float* bo   = (const float*)d_in[9];
    const float* ln1w = (const float*)d_in[10];
    const float* ln1b = (const float*)d_in[11];
    const float* ln2w = (const float*)d_in[12];
    const float* ln2b = (const float*)d_in[13];
    const float* w1   = (const float*)d_in[14];
    const float* b1   = (const float*)d_in[15];
    const float* w2   = (const float*)d_in[16];
    const float* b2   = (const float*)d_in[17];
    const float* outw = (const float*)d_in[18];
    const float* outb = (const float*)d_in[19];

    float *x, *h, *qkv, *ff, *vt, *wqkvT, *woT, *w1T, *w2T, *outwT, *bqkv;
    cudaGetSymbolAddress((void**)&x,     g_x);
    cudaGetSymbolAddress((void**)&h,     g_h);
    cudaGetSymbolAddress((void**)&qkv,   g_qkv);
    cudaGetSymbolAddress((void**)&ff,    g_ff);
    cudaGetSymbolAddress((void**)&vt,    g_vt);
    cudaGetSymbolAddress((void**)&wqkvT, g_wqkvT);
    cudaGetSymbolAddress((void**)&woT,   g_woT);
    cudaGetSymbolAddress((void**)&w1T,   g_w1T);
    cudaGetSymbolAddress((void**)&w2T,   g_w2T);
    cudaGetSymbolAddress((void**)&outwT, g_outwT);
    cudaGetSymbolAddress((void**)&bqkv,  g_bqkv);

    cudaFuncSetAttribute(gemm_cp,  cudaFuncAttributeMaxDynamicSharedMemorySize, GEMM_CP_SMEM);
    cudaFuncSetAttribute(attn_mma, cudaFuncAttributeMaxDynamicSharedMemorySize, ATTN_SMEM);

    dim3 tb(32, 8);

    embed_ln<<<NTOK, 256>>>(ids, emb, ln1w, ln1b, x, h);                       // 1
    transpose_qkv<<<dim3(16, 16, 3 * NL), tb>>>(wq, wk, wv, wqkvT);            // 2
    biaspack_kernel<<<(NL * QKVW + 255) / 256, 256>>>(bq, bk, bv, bqkv);       // 3
    run_gemm_cp(h, wqkvT, bqkv, nullptr, qkv, vt, DM, QKVW, 2);                // 4 <- ncu
    transpose_k<<<dim3(16, 16, NL), tb>>>(wo, woT, DM, DM, (size_t)DM*DM, (size_t)DM*DM);
    transpose_k<<<dim3(DFF/32, 16, NL), tb>>>(w1, w1T, DM, DFF, (size_t)DM*DFF, (size_t)DM*DFF);
    transpose_k<<<dim3(16, DFF/32, NL), tb>>>(w2, w2T, DFF, DM, (size_t)DM*DFF, (size_t)DM*DFF);
    transpose_k<<<dim3(NV/32, 16, 1),   tb>>>(outw, outwT, DM, NV, 0, 0);

    for (int l = 0; l < NL; l++) {
        size_t offD = (size_t)l * DM;
        size_t offF = (size_t)l * DFF;

        if (l > 0) {
            ln_kernel<<<NTOK / 2, 512>>>(x, ln1w + offD, ln1b + offD, h);
            run_gemm_cp(h, wqkvT + (size_t)l * QKVW * DM, bqkv + (size_t)l * QKVW, nullptr,
                        qkv, vt, DM, QKVW, 2);
        }
        attn_mma<<<dim3(SQ / 64, NB * NH), 128, ATTN_SMEM>>>(qkv, vt, h);
        run_gemm_cp(h, woT + (size_t)l * DM * DM, bo + offD, nullptr, x, nullptr, DM, DM, 0);
        ln_kernel<<<NTOK / 2, 512>>>(x, ln2w + offD, ln2b + offD, h);
        run_gemm_cp(h, w1T + (size_t)l * DM * DFF, b1 + offF, nullptr, ff, nullptr, DM, DFF, 1);
        run_gemm_cp(ff, w2T + (size_t)l * DM * DFF, b2 + offD, x /*residual*/, x, nullptr,
                    DFF, DM, (l == NL - 1) ? 2 : 0);
    }

    run_gemm_cp(x, outwT, outb, nullptr, (float*)d_out, nullptr, DM, NV, 0);
}